// round 17
// baseline (speedup 1.0000x reference)
#include <cuda_runtime.h>
#include <cuda_fp16.h>
#include <cstdint>

#define N_NODES 50000
#define DEG     32
#define DFEAT   128
#define DIN     256
#define DOUT    256

#define BM 32
#define XLD 264          // fp16 row stride for xs (pad 8)

// smem: xs hi + lo
#define XS_HI_OFF 0u
#define XS_LO_OFF (BM * XLD * 2u)            // 16896
#define SMEM_BYTES (2u * BM * XLD * 2u)      // 33792

#define F2H_BLOCKS 3125                      // 800000 uint4 / 256

// W (single fp16) in fragment order: [ksg(16)][nblk(32)][lane(32)] -> uint2
__device__ uint2 g_wfrag[16 * 32 * 32];      // 128 KB

// fp16 copy of features, packed 2 cols/word: [node][64] uint32
__device__ uint32_t g_fh[N_NODES * (DFEAT / 2)];   // 12.8 MB

__device__ __forceinline__ void f16x2_split(float x, float y,
                                            uint32_t& hi, uint32_t& lo) {
    __half2 h = __float22half2_rn(make_float2(x, y));
    float2 hf = __half22float2(h);
    __half2 l = __float22half2_rn(make_float2(x - hf.x, y - hf.y));
    hi = *reinterpret_cast<uint32_t*>(&h);
    lo = *reinterpret_cast<uint32_t*>(&l);
}

__device__ __forceinline__ void mma_f16(float* d, const uint32_t* a,
                                        uint32_t b0, uint32_t b1) {
    asm volatile(
        "mma.sync.aligned.m16n8k16.row.col.f32.f16.f16.f32 "
        "{%0,%1,%2,%3}, {%4,%5,%6,%7}, {%8,%9}, {%0,%1,%2,%3};"
        : "+f"(d[0]), "+f"(d[1]), "+f"(d[2]), "+f"(d[3])
        : "r"(a[0]), "r"(a[1]), "r"(a[2]), "r"(a[3]),
          "r"(b0), "r"(b1));
}

// ------------- merged prologue: f2h (blocks <3125) + wsplit ----------------
__global__ void prologue_kernel(const float* __restrict__ F,
                                const float* __restrict__ W) {
    if (blockIdx.x < F2H_BLOCKS) {
        const int idx = blockIdx.x * blockDim.x + threadIdx.x;   // uint4 index
        const float4 v0 = *reinterpret_cast<const float4*>(F + idx * 8);
        const float4 v1 = *reinterpret_cast<const float4*>(F + idx * 8 + 4);
        __half2 p0 = __float22half2_rn(make_float2(v0.x, v0.y));
        __half2 p1 = __float22half2_rn(make_float2(v0.z, v0.w));
        __half2 p2 = __float22half2_rn(make_float2(v1.x, v1.y));
        __half2 p3 = __float22half2_rn(make_float2(v1.z, v1.w));
        uint4 o;
        o.x = *reinterpret_cast<uint32_t*>(&p0);
        o.y = *reinterpret_cast<uint32_t*>(&p1);
        o.z = *reinterpret_cast<uint32_t*>(&p2);
        o.w = *reinterpret_cast<uint32_t*>(&p3);
        *reinterpret_cast<uint4*>(g_fh + idx * 4) = o;
    } else {
        const int idx = (blockIdx.x - F2H_BLOCKS) * blockDim.x + threadIdx.x; // 16384
        const int lane = idx & 31;
        const int nblk = (idx >> 5) & 31;
        const int ksg  = idx >> 10;            // 0..15
        const int g = lane >> 2, t = lane & 3;
        const int n  = nblk * 8 + g;
        const int k0 = ksg * 16 + 2 * t;
        const int k1 = k0 + 8;

        __half2 b0 = __float22half2_rn(make_float2(W[k0 * DOUT + n], W[(k0 + 1) * DOUT + n]));
        __half2 b1 = __float22half2_rn(make_float2(W[k1 * DOUT + n], W[(k1 + 1) * DOUT + n]));
        uint2 v;
        v.x = *reinterpret_cast<uint32_t*>(&b0);
        v.y = *reinterpret_cast<uint32_t*>(&b1);
        g_wfrag[idx] = v;
    }
}

// ------------------------------ fused kernel -------------------------------
__global__ __launch_bounds__(256, 4)
void sage_fused_kernel(const float* __restrict__ features,
                       const int* __restrict__ edges,
                       float* __restrict__ out)
{
    extern __shared__ char sm[];
    uint32_t* xs_hi = reinterpret_cast<uint32_t*>(sm + XS_HI_OFF);
    uint32_t* xs_lo = reinterpret_cast<uint32_t*>(sm + XS_LO_OFF);

    const int tid  = threadIdx.x;
    const int lane = tid & 31;
    const int wid  = tid >> 5;            // 0..7
    const int node0 = blockIdx.x * BM;

    // ---------------- Phase 1: gather + mean + split ------------------------
    // Lanes 0-15 handle even neighbor rows, 16-31 odd. Rows pre-summed in
    // PAIRS with HADD2 (values sigma~1.4, fp16 exact enough), then converted
    // once -> 33% fewer unpack/add slots. One shfl_down(16) merges halves.
    const int half = lane >> 4;           // 0 or 1
    const int lL   = lane & 15;

    #pragma unroll
    for (int s = 0; s < BM / 8; s++) {
        const int m = wid * (BM / 8) + s;
        const int node = node0 + m;
        const int wbase = m * (XLD / 2);
        if (node < N_NODES) {
            const int my_e = edges[node * DEG + lane];

            float acc8[8];
            #pragma unroll
            for (int r = 0; r < 8; r++) acc8[r] = 0.f;

            #pragma unroll
            for (int q2 = 0; q2 < DEG / 4; q2++) {
                const int ja = 4 * q2 + half;
                const int jb = ja + 2;
                const int ia = __shfl_sync(0xffffffffu, my_e, ja);
                const int ib = __shfl_sync(0xffffffffu, my_e, jb);
                const uint4 wa = *reinterpret_cast<const uint4*>(
                    g_fh + ia * (DFEAT / 2) + lL * 4);
                const uint4 wb = *reinterpret_cast<const uint4*>(
                    g_fh + ib * (DFEAT / 2) + lL * 4);
                // pairwise fp16 pre-reduction
                __half2 s0 = __hadd2(*reinterpret_cast<const __half2*>(&wa.x),
                                     *reinterpret_cast<const __half2*>(&wb.x));
                __half2 s1 = __hadd2(*reinterpret_cast<const __half2*>(&wa.y),
                                     *reinterpret_cast<const __half2*>(&wb.y));
                __half2 s2 = __hadd2(*reinterpret_cast<const __half2*>(&wa.z),
                                     *reinterpret_cast<const __half2*>(&wb.z));
                __half2 s3 = __hadd2(*reinterpret_cast<const __half2*>(&wa.w),
                                     *reinterpret_cast<const __half2*>(&wb.w));
                const float2 f0 = __half22float2(s0);
                const float2 f1 = __half22float2(s1);
                const float2 f2 = __half22float2(s2);
                const float2 f3 = __half22float2(s3);
                acc8[0] += f0.x; acc8[1] += f0.y;
                acc8[2] += f1.x; acc8[3] += f1.y;
                acc8[4] += f2.x; acc8[5] += f2.y;
                acc8[6] += f3.x; acc8[7] += f3.y;
            }
            // fold odd-row partial sums (lanes 16-31) into lanes 0-15
            #pragma unroll
            for (int r = 0; r < 8; r++)
                acc8[r] += __shfl_down_sync(0xffffffffu, acc8[r], 16);

            if (half == 0) {
                // lanes 0-15: scale, split, store AGG cols [8lL..8lL+8)
                const float inv = 1.0f / (float)DEG;
                uint32_t h[4], l[4];
                #pragma unroll
                for (int r = 0; r < 4; r++)
                    f16x2_split(acc8[2 * r] * inv, acc8[2 * r + 1] * inv, h[r], l[r]);
                *reinterpret_cast<uint4*>(xs_hi + wbase + 64 + lL * 4) =
                    make_uint4(h[0], h[1], h[2], h[3]);
                *reinterpret_cast<uint4*>(xs_lo + wbase + 64 + lL * 4) =
                    make_uint4(l[0], l[1], l[2], l[3]);
            } else {
                // lanes 16-31: load fp32 SELF cols [8lL..8lL+8), split, store
                const float4 s0 = *reinterpret_cast<const float4*>(
                    features + (long long)node * DFEAT + lL * 8);
                const float4 s1 = *reinterpret_cast<const float4*>(
                    features + (long long)node * DFEAT + lL * 8 + 4);
                uint32_t h[4], l[4];
                f16x2_split(s0.x, s0.y, h[0], l[0]);
                f16x2_split(s0.z, s0.w, h[1], l[1]);
                f16x2_split(s1.x, s1.y, h[2], l[2]);
                f16x2_split(s1.z, s1.w, h[3], l[3]);
                *reinterpret_cast<uint4*>(xs_hi + wbase + lL * 4) =
                    make_uint4(h[0], h[1], h[2], h[3]);
                *reinterpret_cast<uint4*>(xs_lo + wbase + lL * 4) =
                    make_uint4(l[0], l[1], l[2], l[3]);
            }
        } else {
            const uint4 z = make_uint4(0u, 0u, 0u, 0u);
            const int off = (half == 0) ? 64 : 0;
            *reinterpret_cast<uint4*>(xs_hi + wbase + off + lL * 4) = z;
            *reinterpret_cast<uint4*>(xs_lo + wbase + off + lL * 4) = z;
        }
    }
    __syncthreads();

    // ---------------- Phase 2: fp16x2 GEMM, B direct from L2 ---------------
    // 8 warps, each owns M=32 x 32 N-cols; mt SEQUENTIAL to fit 64 regs.
    const int g  = lane >> 2;
    const int t  = lane & 3;
    const int n_base = wid * 32;

    float acc[2][4][4];
    #pragma unroll
    for (int mt = 0; mt < 2; mt++)
        #pragma unroll
        for (int nt = 0; nt < 4; nt++)
            #pragma unroll
            for (int r = 0; r < 4; r++)
                acc[mt][nt][r] = 0.f;

    // nblk = wid*4 + nt
    const uint2* wbase_p = g_wfrag + (wid * 4) * 32 + lane;

    #pragma unroll 1
    for (int ksg = 0; ksg < 16; ksg++) {
        uint2 bw[4];
        #pragma unroll
        for (int q = 0; q < 4; q++)
            bw[q] = wbase_p[(ksg * 32 + q) * 32];

        #pragma unroll
        for (int mt = 0; mt < 2; mt++) {
            const int r0 = mt * 16 + g;
            const int i00 = r0 * (XLD / 2) + ksg * 8 + t;
            const int i01 = (r0 + 8) * (XLD / 2) + ksg * 8 + t;
            uint32_t ah[4], al[4];
            ah[0] = xs_hi[i00];     al[0] = xs_lo[i00];
            ah[1] = xs_hi[i01];     al[1] = xs_lo[i01];
            ah[2] = xs_hi[i00 + 4]; al[2] = xs_lo[i00 + 4];
            ah[3] = xs_hi[i01 + 4]; al[3] = xs_lo[i01 + 4];

            #pragma unroll
            for (int nt = 0; nt < 4; nt++) {
                mma_f16(acc[mt][nt], ah, bw[nt].x, bw[nt].y);  // Ah*W
                mma_f16(acc[mt][nt], al, bw[nt].x, bw[nt].y);  // Al*W
            }
        }
    }

    // ---------------- Phase 3: ReLU + store from registers -----------------
    #pragma unroll
    for (int mt = 0; mt < 2; mt++) {
        const int r0 = node0 + mt * 16 + g;
        #pragma unroll
        for (int nt = 0; nt < 4; nt++) {
            const int c0 = n_base + nt * 8 + t * 2;
            if (r0 < N_NODES) {
                float2 v0 = make_float2(fmaxf(acc[mt][nt][0], 0.f),
                                        fmaxf(acc[mt][nt][1], 0.f));
                *reinterpret_cast<float2*>(out + (long long)r0 * DOUT + c0) = v0;
            }
            if (r0 + 8 < N_NODES) {
                float2 v1 = make_float2(fmaxf(acc[mt][nt][2], 0.f),
                                        fmaxf(acc[mt][nt][3], 0.f));
                *reinterpret_cast<float2*>(out + (long long)(r0 + 8) * DOUT + c0) = v1;
            }
        }
    }
}

extern "C" void kernel_launch(void* const* d_in, const int* in_sizes, int n_in,
                              void* d_out, int out_size)
{
    const float* features = (const float*)d_in[0];
    const int*   edges    = (const int*)d_in[1];
    const float* kernel   = (const float*)d_in[2];
    float*       out      = (float*)d_out;
    (void)in_sizes; (void)n_in; (void)out_size;

    static bool attr_set = false;
    if (!attr_set) {
        cudaFuncSetAttribute(sage_fused_kernel,
                             cudaFuncAttributeMaxDynamicSharedMemorySize, SMEM_BYTES);
        attr_set = true;
    }

    prologue_kernel<<<F2H_BLOCKS + 64, 256>>>(features, kernel);
    const int grid = (N_NODES + BM - 1) / BM;   // 1563
    sage_fused_kernel<<<grid, 256, SMEM_BYTES>>>(features, edges, out);
}